// round 1
// baseline (speedup 1.0000x reference)
#include <cuda_runtime.h>

// AttentionAutoInt: out = relu(x@Wr + softmax((x@Wq)(x@Wk)^T) @ (x@Wv))
// B=8192, M=64, D=DP=128, fp32.
//
// Round-0 baseline: fully fused, one CTA per batch, fp32 CUDA-core math.
// smem: x tile + staged weight + padded q/k/v tiles + scores = 211 KB, 1 CTA/SM.

static constexpr int Mdim = 64;
static constexpr int Ddim = 128;
static constexpr int QS   = 132;   // padded row stride (floats) for q/k/v: kills
                                   // the 32-way LDS bank conflict in the scores
                                   // phase (132 mod 32 = 4 -> worst case 4-way)
static constexpr int NTHREADS = 512;

static constexpr int OFF_XS = 0;                    // x   [64][128]
static constexpr int OFF_WS = OFF_XS + Mdim * Ddim; // W   [128][128] (staged per projection)
static constexpr int OFF_QS = OFF_WS + Ddim * Ddim; // q   [64][132]
static constexpr int OFF_KS = OFF_QS + Mdim * QS;   // k   [64][132]
static constexpr int OFF_VS = OFF_KS + Mdim * QS;   // v   [64][132]
static constexpr int OFF_SS = OFF_VS + Mdim * QS;   // s   [64][64]
static constexpr int SMEM_FLOATS = OFF_SS + Mdim * Mdim;
static constexpr int SMEM_BYTES  = SMEM_FLOATS * (int)sizeof(float); // 216064

// Stage a 128x128 fp32 weight matrix from gmem (L2-resident) into smem.
__device__ __forceinline__ void stage_weight(const float* __restrict__ g,
                                             float* __restrict__ ws, int tid) {
    const float4* g4 = reinterpret_cast<const float4*>(g);
    float4* w4 = reinterpret_cast<float4*>(ws);
#pragma unroll
    for (int i = 0; i < 8; i++) w4[tid + i * NTHREADS] = g4[tid + i * NTHREADS];
}

// dst[m][e] = sum_d xs[m][d] * ws[d][e].
// Warp w owns rows m0..m0+3; lane owns 4 consecutive e-columns (float4).
// Per d: 1 LDS.128 (weights, conflict-free) + 4 LDS.32 (x, broadcast) + 16 FFMA.
__device__ __forceinline__ void gemm_xw(const float* __restrict__ xs,
                                        const float* __restrict__ ws,
                                        float* __restrict__ dst,
                                        int w, int ln) {
    const int m0 = w * 4;
    float4 a0 = make_float4(0.f, 0.f, 0.f, 0.f), a1 = a0, a2 = a0, a3 = a0;
#pragma unroll 4
    for (int d = 0; d < Ddim; d++) {
        const float4 wv = *reinterpret_cast<const float4*>(ws + d * Ddim + ln * 4);
        const float x0 = xs[(m0 + 0) * Ddim + d];
        const float x1 = xs[(m0 + 1) * Ddim + d];
        const float x2 = xs[(m0 + 2) * Ddim + d];
        const float x3 = xs[(m0 + 3) * Ddim + d];
        a0.x = fmaf(x0, wv.x, a0.x); a0.y = fmaf(x0, wv.y, a0.y);
        a0.z = fmaf(x0, wv.z, a0.z); a0.w = fmaf(x0, wv.w, a0.w);
        a1.x = fmaf(x1, wv.x, a1.x); a1.y = fmaf(x1, wv.y, a1.y);
        a1.z = fmaf(x1, wv.z, a1.z); a1.w = fmaf(x1, wv.w, a1.w);
        a2.x = fmaf(x2, wv.x, a2.x); a2.y = fmaf(x2, wv.y, a2.y);
        a2.z = fmaf(x2, wv.z, a2.z); a2.w = fmaf(x2, wv.w, a2.w);
        a3.x = fmaf(x3, wv.x, a3.x); a3.y = fmaf(x3, wv.y, a3.y);
        a3.z = fmaf(x3, wv.z, a3.z); a3.w = fmaf(x3, wv.w, a3.w);
    }
    *reinterpret_cast<float4*>(dst + (m0 + 0) * QS + ln * 4) = a0;
    *reinterpret_cast<float4*>(dst + (m0 + 1) * QS + ln * 4) = a1;
    *reinterpret_cast<float4*>(dst + (m0 + 2) * QS + ln * 4) = a2;
    *reinterpret_cast<float4*>(dst + (m0 + 3) * QS + ln * 4) = a3;
}

__global__ __launch_bounds__(NTHREADS, 1)
void autoint_kernel(const float* __restrict__ x,
                    const float* __restrict__ Wq, const float* __restrict__ Wk,
                    const float* __restrict__ Wv, const float* __restrict__ Wr,
                    float* __restrict__ out) {
    extern __shared__ float sm[];
    float* xs = sm + OFF_XS;
    float* ws = sm + OFF_WS;
    float* qs = sm + OFF_QS;
    float* ks = sm + OFF_KS;
    float* vs = sm + OFF_VS;
    float* ss = sm + OFF_SS;

    const int b   = blockIdx.x;
    const int tid = threadIdx.x;
    const int w   = tid >> 5;
    const int ln  = tid & 31;

    // ---- P1: load x[b] (64x128) ----
    {
        const float4* gx = reinterpret_cast<const float4*>(x + (size_t)b * Mdim * Ddim);
        float4* xs4 = reinterpret_cast<float4*>(xs);
#pragma unroll
        for (int i = 0; i < 4; i++) xs4[tid + i * NTHREADS] = gx[tid + i * NTHREADS];
    }
    __syncthreads();

    // ---- P2: q, k, v projections (weight staged through smem) ----
    stage_weight(Wq, ws, tid); __syncthreads();
    gemm_xw(xs, ws, qs, w, ln); __syncthreads();
    stage_weight(Wk, ws, tid); __syncthreads();
    gemm_xw(xs, ws, ks, w, ln); __syncthreads();
    stage_weight(Wv, ws, tid); __syncthreads();
    gemm_xw(xs, ws, vs, w, ln); __syncthreads();

    // ---- P3: scores s[m][n] = q[m,:] . k[n,:]  (warp: 4 m-rows; lane: n, n+32) ----
    {
        const int m0 = w * 4;
        float acc0[4] = {0.f, 0.f, 0.f, 0.f};
        float acc1[4] = {0.f, 0.f, 0.f, 0.f};
#pragma unroll 2
        for (int d = 0; d < Ddim; d += 4) {
            const float4 k0 = *reinterpret_cast<const float4*>(ks + ln * QS + d);
            const float4 k1 = *reinterpret_cast<const float4*>(ks + (ln + 32) * QS + d);
#pragma unroll
            for (int mi = 0; mi < 4; mi++) {
                const float4 qv = *reinterpret_cast<const float4*>(qs + (m0 + mi) * QS + d);
                acc0[mi] = fmaf(qv.x, k0.x, fmaf(qv.y, k0.y, fmaf(qv.z, k0.z, fmaf(qv.w, k0.w, acc0[mi]))));
                acc1[mi] = fmaf(qv.x, k1.x, fmaf(qv.y, k1.y, fmaf(qv.z, k1.z, fmaf(qv.w, k1.w, acc1[mi]))));
            }
        }
#pragma unroll
        for (int mi = 0; mi < 4; mi++) {
            ss[(m0 + mi) * Mdim + ln]      = acc0[mi];
            ss[(m0 + mi) * Mdim + ln + 32] = acc1[mi];
        }
    }
    __syncthreads();

    // ---- P4: softmax over n (each warp: 4 rows) ----
    {
        const int m0 = w * 4;
#pragma unroll
        for (int mi = 0; mi < 4; mi++) {
            const int m = m0 + mi;
            float s0 = ss[m * Mdim + ln];
            float s1 = ss[m * Mdim + ln + 32];
            float mx = fmaxf(s0, s1);
#pragma unroll
            for (int o = 16; o > 0; o >>= 1) mx = fmaxf(mx, __shfl_xor_sync(0xffffffffu, mx, o));
            const float e0 = __expf(s0 - mx);
            const float e1 = __expf(s1 - mx);
            float sum = e0 + e1;
#pragma unroll
            for (int o = 16; o > 0; o >>= 1) sum += __shfl_xor_sync(0xffffffffu, sum, o);
            const float inv = 1.0f / sum;
            ss[m * Mdim + ln]      = e0 * inv;
            ss[m * Mdim + ln + 32] = e1 * inv;
        }
    }
    __syncthreads();

    // ---- P5: stage Wr (r projection fused into epilogue) ----
    stage_weight(Wr, ws, tid);
    __syncthreads();

    // ---- P6: out[m][e] = relu( x@Wr + alphas @ v ) ----
    {
        const int m0 = w * 4;
        float4 a0 = make_float4(0.f, 0.f, 0.f, 0.f), a1 = a0, a2 = a0, a3 = a0;

        // r part: same microtile as gemm_xw
#pragma unroll 4
        for (int d = 0; d < Ddim; d++) {
            const float4 wv = *reinterpret_cast<const float4*>(ws + d * Ddim + ln * 4);
            const float x0 = xs[(m0 + 0) * Ddim + d];
            const float x1 = xs[(m0 + 1) * Ddim + d];
            const float x2 = xs[(m0 + 2) * Ddim + d];
            const float x3 = xs[(m0 + 3) * Ddim + d];
            a0.x = fmaf(x0, wv.x, a0.x); a0.y = fmaf(x0, wv.y, a0.y);
            a0.z = fmaf(x0, wv.z, a0.z); a0.w = fmaf(x0, wv.w, a0.w);
            a1.x = fmaf(x1, wv.x, a1.x); a1.y = fmaf(x1, wv.y, a1.y);
            a1.z = fmaf(x1, wv.z, a1.z); a1.w = fmaf(x1, wv.w, a1.w);
            a2.x = fmaf(x2, wv.x, a2.x); a2.y = fmaf(x2, wv.y, a2.y);
            a2.z = fmaf(x2, wv.z, a2.z); a2.w = fmaf(x2, wv.w, a2.w);
            a3.x = fmaf(x3, wv.x, a3.x); a3.y = fmaf(x3, wv.y, a3.y);
            a3.z = fmaf(x3, wv.z, a3.z); a3.w = fmaf(x3, wv.w, a3.w);
        }

        // attention part: acc += alphas[m][n] * v[n][e]
#pragma unroll 4
        for (int n = 0; n < Mdim; n++) {
            const float4 vv = *reinterpret_cast<const float4*>(vs + n * QS + ln * 4);
            const float p0 = ss[(m0 + 0) * Mdim + n];
            const float p1 = ss[(m0 + 1) * Mdim + n];
            const float p2 = ss[(m0 + 2) * Mdim + n];
            const float p3 = ss[(m0 + 3) * Mdim + n];
            a0.x = fmaf(p0, vv.x, a0.x); a0.y = fmaf(p0, vv.y, a0.y);
            a0.z = fmaf(p0, vv.z, a0.z); a0.w = fmaf(p0, vv.w, a0.w);
            a1.x = fmaf(p1, vv.x, a1.x); a1.y = fmaf(p1, vv.y, a1.y);
            a1.z = fmaf(p1, vv.z, a1.z); a1.w = fmaf(p1, vv.w, a1.w);
            a2.x = fmaf(p2, vv.x, a2.x); a2.y = fmaf(p2, vv.y, a2.y);
            a2.z = fmaf(p2, vv.z, a2.z); a2.w = fmaf(p2, vv.w, a2.w);
            a3.x = fmaf(p3, vv.x, a3.x); a3.y = fmaf(p3, vv.y, a3.y);
            a3.z = fmaf(p3, vv.z, a3.z); a3.w = fmaf(p3, vv.w, a3.w);
        }

        float4* out4 = reinterpret_cast<float4*>(out + (size_t)b * Mdim * Ddim);
        float4 r0, r1, r2, r3;
        r0.x = fmaxf(a0.x, 0.f); r0.y = fmaxf(a0.y, 0.f); r0.z = fmaxf(a0.z, 0.f); r0.w = fmaxf(a0.w, 0.f);
        r1.x = fmaxf(a1.x, 0.f); r1.y = fmaxf(a1.y, 0.f); r1.z = fmaxf(a1.z, 0.f); r1.w = fmaxf(a1.w, 0.f);
        r2.x = fmaxf(a2.x, 0.f); r2.y = fmaxf(a2.y, 0.f); r2.z = fmaxf(a2.z, 0.f); r2.w = fmaxf(a2.w, 0.f);
        r3.x = fmaxf(a3.x, 0.f); r3.y = fmaxf(a3.y, 0.f); r3.z = fmaxf(a3.z, 0.f); r3.w = fmaxf(a3.w, 0.f);
        out4[(m0 + 0) * 32 + ln] = r0;
        out4[(m0 + 1) * 32 + ln] = r1;
        out4[(m0 + 2) * 32 + ln] = r2;
        out4[(m0 + 3) * 32 + ln] = r3;
    }
}

extern "C" void kernel_launch(void* const* d_in, const int* in_sizes, int n_in,
                              void* d_out, int out_size) {
    const float* x  = (const float*)d_in[0];
    const float* Wq = (const float*)d_in[1];
    const float* Wk = (const float*)d_in[2];
    const float* Wv = (const float*)d_in[3];
    const float* Wr = (const float*)d_in[4];
    float* out = (float*)d_out;

    cudaFuncSetAttribute(autoint_kernel,
                         cudaFuncAttributeMaxDynamicSharedMemorySize, SMEM_BYTES);
    autoint_kernel<<<8192, NTHREADS, SMEM_BYTES>>>(x, Wq, Wk, Wv, Wr, out);
}

// round 2
// speedup vs baseline: 1.0001x; 1.0001x over previous
#include <cuda_runtime.h>

// AttentionAutoInt: out = relu(x@Wr + softmax((x@Wq)(x@Wk)^T) @ (x@Wv))
// B=8192, M=64, D=DP=128, fp32.
//
// Round-0 baseline: fully fused, one CTA per batch, fp32 CUDA-core math.
// smem: x tile + staged weight + padded q/k/v tiles + scores = 211 KB, 1 CTA/SM.

static constexpr int Mdim = 64;
static constexpr int Ddim = 128;
static constexpr int QS   = 132;   // padded row stride (floats) for q/k/v: kills
                                   // the 32-way LDS bank conflict in the scores
                                   // phase (132 mod 32 = 4 -> worst case 4-way)
static constexpr int NTHREADS = 512;

static constexpr int OFF_XS = 0;                    // x   [64][128]
static constexpr int OFF_WS = OFF_XS + Mdim * Ddim; // W   [128][128] (staged per projection)
static constexpr int OFF_QS = OFF_WS + Ddim * Ddim; // q   [64][132]
static constexpr int OFF_KS = OFF_QS + Mdim * QS;   // k   [64][132]
static constexpr int OFF_VS = OFF_KS + Mdim * QS;   // v   [64][132]
static constexpr int OFF_SS = OFF_VS + Mdim * QS;   // s   [64][64]
static constexpr int SMEM_FLOATS = OFF_SS + Mdim * Mdim;
static constexpr int SMEM_BYTES  = SMEM_FLOATS * (int)sizeof(float); // 216064

// Stage a 128x128 fp32 weight matrix from gmem (L2-resident) into smem.
__device__ __forceinline__ void stage_weight(const float* __restrict__ g,
                                             float* __restrict__ ws, int tid) {
    const float4* g4 = reinterpret_cast<const float4*>(g);
    float4* w4 = reinterpret_cast<float4*>(ws);
#pragma unroll
    for (int i = 0; i < 8; i++) w4[tid + i * NTHREADS] = g4[tid + i * NTHREADS];
}

// dst[m][e] = sum_d xs[m][d] * ws[d][e].
// Warp w owns rows m0..m0+3; lane owns 4 consecutive e-columns (float4).
// Per d: 1 LDS.128 (weights, conflict-free) + 4 LDS.32 (x, broadcast) + 16 FFMA.
__device__ __forceinline__ void gemm_xw(const float* __restrict__ xs,
                                        const float* __restrict__ ws,
                                        float* __restrict__ dst,
                                        int w, int ln) {
    const int m0 = w * 4;
    float4 a0 = make_float4(0.f, 0.f, 0.f, 0.f), a1 = a0, a2 = a0, a3 = a0;
#pragma unroll 4
    for (int d = 0; d < Ddim; d++) {
        const float4 wv = *reinterpret_cast<const float4*>(ws + d * Ddim + ln * 4);
        const float x0 = xs[(m0 + 0) * Ddim + d];
        const float x1 = xs[(m0 + 1) * Ddim + d];
        const float x2 = xs[(m0 + 2) * Ddim + d];
        const float x3 = xs[(m0 + 3) * Ddim + d];
        a0.x = fmaf(x0, wv.x, a0.x); a0.y = fmaf(x0, wv.y, a0.y);
        a0.z = fmaf(x0, wv.z, a0.z); a0.w = fmaf(x0, wv.w, a0.w);
        a1.x = fmaf(x1, wv.x, a1.x); a1.y = fmaf(x1, wv.y, a1.y);
        a1.z = fmaf(x1, wv.z, a1.z); a1.w = fmaf(x1, wv.w, a1.w);
        a2.x = fmaf(x2, wv.x, a2.x); a2.y = fmaf(x2, wv.y, a2.y);
        a2.z = fmaf(x2, wv.z, a2.z); a2.w = fmaf(x2, wv.w, a2.w);
        a3.x = fmaf(x3, wv.x, a3.x); a3.y = fmaf(x3, wv.y, a3.y);
        a3.z = fmaf(x3, wv.z, a3.z); a3.w = fmaf(x3, wv.w, a3.w);
    }
    *reinterpret_cast<float4*>(dst + (m0 + 0) * QS + ln * 4) = a0;
    *reinterpret_cast<float4*>(dst + (m0 + 1) * QS + ln * 4) = a1;
    *reinterpret_cast<float4*>(dst + (m0 + 2) * QS + ln * 4) = a2;
    *reinterpret_cast<float4*>(dst + (m0 + 3) * QS + ln * 4) = a3;
}

__global__ __launch_bounds__(NTHREADS, 1)
void autoint_kernel(const float* __restrict__ x,
                    const float* __restrict__ Wq, const float* __restrict__ Wk,
                    const float* __restrict__ Wv, const float* __restrict__ Wr,
                    float* __restrict__ out) {
    extern __shared__ float sm[];
    float* xs = sm + OFF_XS;
    float* ws = sm + OFF_WS;
    float* qs = sm + OFF_QS;
    float* ks = sm + OFF_KS;
    float* vs = sm + OFF_VS;
    float* ss = sm + OFF_SS;

    const int b   = blockIdx.x;
    const int tid = threadIdx.x;
    const int w   = tid >> 5;
    const int ln  = tid & 31;

    // ---- P1: load x[b] (64x128) ----
    {
        const float4* gx = reinterpret_cast<const float4*>(x + (size_t)b * Mdim * Ddim);
        float4* xs4 = reinterpret_cast<float4*>(xs);
#pragma unroll
        for (int i = 0; i < 4; i++) xs4[tid + i * NTHREADS] = gx[tid + i * NTHREADS];
    }
    __syncthreads();

    // ---- P2: q, k, v projections (weight staged through smem) ----
    stage_weight(Wq, ws, tid); __syncthreads();
    gemm_xw(xs, ws, qs, w, ln); __syncthreads();
    stage_weight(Wk, ws, tid); __syncthreads();
    gemm_xw(xs, ws, ks, w, ln); __syncthreads();
    stage_weight(Wv, ws, tid); __syncthreads();
    gemm_xw(xs, ws, vs, w, ln); __syncthreads();

    // ---- P3: scores s[m][n] = q[m,:] . k[n,:]  (warp: 4 m-rows; lane: n, n+32) ----
    {
        const int m0 = w * 4;
        float acc0[4] = {0.f, 0.f, 0.f, 0.f};
        float acc1[4] = {0.f, 0.f, 0.f, 0.f};
#pragma unroll 2
        for (int d = 0; d < Ddim; d += 4) {
            const float4 k0 = *reinterpret_cast<const float4*>(ks + ln * QS + d);
            const float4 k1 = *reinterpret_cast<const float4*>(ks + (ln + 32) * QS + d);
#pragma unroll
            for (int mi = 0; mi < 4; mi++) {
                const float4 qv = *reinterpret_cast<const float4*>(qs + (m0 + mi) * QS + d);
                acc0[mi] = fmaf(qv.x, k0.x, fmaf(qv.y, k0.y, fmaf(qv.z, k0.z, fmaf(qv.w, k0.w, acc0[mi]))));
                acc1[mi] = fmaf(qv.x, k1.x, fmaf(qv.y, k1.y, fmaf(qv.z, k1.z, fmaf(qv.w, k1.w, acc1[mi]))));
            }
        }
#pragma unroll
        for (int mi = 0; mi < 4; mi++) {
            ss[(m0 + mi) * Mdim + ln]      = acc0[mi];
            ss[(m0 + mi) * Mdim + ln + 32] = acc1[mi];
        }
    }
    __syncthreads();

    // ---- P4: softmax over n (each warp: 4 rows) ----
    {
        const int m0 = w * 4;
#pragma unroll
        for (int mi = 0; mi < 4; mi++) {
            const int m = m0 + mi;
            float s0 = ss[m * Mdim + ln];
            float s1 = ss[m * Mdim + ln + 32];
            float mx = fmaxf(s0, s1);
#pragma unroll
            for (int o = 16; o > 0; o >>= 1) mx = fmaxf(mx, __shfl_xor_sync(0xffffffffu, mx, o));
            const float e0 = __expf(s0 - mx);
            const float e1 = __expf(s1 - mx);
            float sum = e0 + e1;
#pragma unroll
            for (int o = 16; o > 0; o >>= 1) sum += __shfl_xor_sync(0xffffffffu, sum, o);
            const float inv = 1.0f / sum;
            ss[m * Mdim + ln]      = e0 * inv;
            ss[m * Mdim + ln + 32] = e1 * inv;
        }
    }
    __syncthreads();

    // ---- P5: stage Wr (r projection fused into epilogue) ----
    stage_weight(Wr, ws, tid);
    __syncthreads();

    // ---- P6: out[m][e] = relu( x@Wr + alphas @ v ) ----
    {
        const int m0 = w * 4;
        float4 a0 = make_float4(0.f, 0.f, 0.f, 0.f), a1 = a0, a2 = a0, a3 = a0;

        // r part: same microtile as gemm_xw
#pragma unroll 4
        for (int d = 0; d < Ddim; d++) {
            const float4 wv = *reinterpret_cast<const float4*>(ws + d * Ddim + ln * 4);
            const float x0 = xs[(m0 + 0) * Ddim + d];
            const float x1 = xs[(m0 + 1) * Ddim + d];
            const float x2 = xs[(m0 + 2) * Ddim + d];
            const float x3 = xs[(m0 + 3) * Ddim + d];
            a0.x = fmaf(x0, wv.x, a0.x); a0.y = fmaf(x0, wv.y, a0.y);
            a0.z = fmaf(x0, wv.z, a0.z); a0.w = fmaf(x0, wv.w, a0.w);
            a1.x = fmaf(x1, wv.x, a1.x); a1.y = fmaf(x1, wv.y, a1.y);
            a1.z = fmaf(x1, wv.z, a1.z); a1.w = fmaf(x1, wv.w, a1.w);
            a2.x = fmaf(x2, wv.x, a2.x); a2.y = fmaf(x2, wv.y, a2.y);
            a2.z = fmaf(x2, wv.z, a2.z); a2.w = fmaf(x2, wv.w, a2.w);
            a3.x = fmaf(x3, wv.x, a3.x); a3.y = fmaf(x3, wv.y, a3.y);
            a3.z = fmaf(x3, wv.z, a3.z); a3.w = fmaf(x3, wv.w, a3.w);
        }

        // attention part: acc += alphas[m][n] * v[n][e]
#pragma unroll 4
        for (int n = 0; n < Mdim; n++) {
            const float4 vv = *reinterpret_cast<const float4*>(vs + n * QS + ln * 4);
            const float p0 = ss[(m0 + 0) * Mdim + n];
            const float p1 = ss[(m0 + 1) * Mdim + n];
            const float p2 = ss[(m0 + 2) * Mdim + n];
            const float p3 = ss[(m0 + 3) * Mdim + n];
            a0.x = fmaf(p0, vv.x, a0.x); a0.y = fmaf(p0, vv.y, a0.y);
            a0.z = fmaf(p0, vv.z, a0.z); a0.w = fmaf(p0, vv.w, a0.w);
            a1.x = fmaf(p1, vv.x, a1.x); a1.y = fmaf(p1, vv.y, a1.y);
            a1.z = fmaf(p1, vv.z, a1.z); a1.w = fmaf(p1, vv.w, a1.w);
            a2.x = fmaf(p2, vv.x, a2.x); a2.y = fmaf(p2, vv.y, a2.y);
            a2.z = fmaf(p2, vv.z, a2.z); a2.w = fmaf(p2, vv.w, a2.w);
            a3.x = fmaf(p3, vv.x, a3.x); a3.y = fmaf(p3, vv.y, a3.y);
            a3.z = fmaf(p3, vv.z, a3.z); a3.w = fmaf(p3, vv.w, a3.w);
        }

        float4* out4 = reinterpret_cast<float4*>(out + (size_t)b * Mdim * Ddim);
        float4 r0, r1, r2, r3;
        r0.x = fmaxf(a0.x, 0.f); r0.y = fmaxf(a0.y, 0.f); r0.z = fmaxf(a0.z, 0.f); r0.w = fmaxf(a0.w, 0.f);
        r1.x = fmaxf(a1.x, 0.f); r1.y = fmaxf(a1.y, 0.f); r1.z = fmaxf(a1.z, 0.f); r1.w = fmaxf(a1.w, 0.f);
        r2.x = fmaxf(a2.x, 0.f); r2.y = fmaxf(a2.y, 0.f); r2.z = fmaxf(a2.z, 0.f); r2.w = fmaxf(a2.w, 0.f);
        r3.x = fmaxf(a3.x, 0.f); r3.y = fmaxf(a3.y, 0.f); r3.z = fmaxf(a3.z, 0.f); r3.w = fmaxf(a3.w, 0.f);
        out4[(m0 + 0) * 32 + ln] = r0;
        out4[(m0 + 1) * 32 + ln] = r1;
        out4[(m0 + 2) * 32 + ln] = r2;
        out4[(m0 + 3) * 32 + ln] = r3;
    }
}

extern "C" void kernel_launch(void* const* d_in, const int* in_sizes, int n_in,
                              void* d_out, int out_size) {
    const float* x  = (const float*)d_in[0];
    const float* Wq = (const float*)d_in[1];
    const float* Wk = (const float*)d_in[2];
    const float* Wv = (const float*)d_in[3];
    const float* Wr = (const float*)d_in[4];
    float* out = (float*)d_out;

    cudaFuncSetAttribute(autoint_kernel,
                         cudaFuncAttributeMaxDynamicSharedMemorySize, SMEM_BYTES);
    autoint_kernel<<<8192, NTHREADS, SMEM_BYTES>>>(x, Wq, Wk, Wv, Wr, out);
}